// round 3
// baseline (speedup 1.0000x reference)
#include <cuda_runtime.h>
#include <math.h>

#define NN 50000
#define EE 800000
#define IN_DIM 200
#define HD 128
#define DD 127
#define GG 512
#define EPSF 1e-5f

// ---------------- scratch (device globals; no allocation allowed) ----------------
__device__ float g_h[NN * HD];      // current node features (hyperboloid points)
__device__ float g_u[NN * HD];      // logmap0 spatial (slots 0..126, slot 127 = 0)
__device__ float g_p[NN * HD];      // GEMM output (slots 0..126, slot 127 = 0)
__device__ float g_hl[NN * HD];     // attention-linear hyperboloid points
__device__ float g_m[NN * HD];      // centroid accumulator
__device__ float g_wt[6 * HD * HD]; // transposed+padded layer weights (att l0, att l1, mlp 00,01,10,11)
__device__ float g_wtin[IN_DIM * HD]; // padded input weight

__device__ __forceinline__ float warp_sum(float v) {
#pragma unroll
    for (int o = 16; o; o >>= 1) v += __shfl_xor_sync(0xffffffffu, v, o);
    return v;
}

// ---------------- utility kernels ----------------
__global__ void zero4_kernel(float4* __restrict__ p, int n4) {
    int i = blockIdx.x * blockDim.x + threadIdx.x;
    if (i < n4) p[i] = make_float4(0.f, 0.f, 0.f, 0.f);
}

// wt[w][k*128 + j] = W_w[j][k]  (transpose so GEMM loads are coalesced over j)
__global__ void prep_weights(const float* __restrict__ att_w, const float* __restrict__ mlp_w) {
    int idx = blockIdx.x * blockDim.x + threadIdx.x;
    if (idx >= 6 * HD * HD) return;
    int w = idx >> 14;
    int k = (idx >> 7) & 127;
    int j = idx & 127;
    float val = 0.f;
    if (k < DD && j < DD) {
        const float* src = (w < 2) ? (att_w + w * DD * DD) : (mlp_w + (w - 2) * DD * DD);
        val = src[j * DD + k];
    }
    g_wt[idx] = val;
}

__global__ void prep_win(const float* __restrict__ w_in) {
    int idx = blockIdx.x * blockDim.x + threadIdx.x;
    if (idx >= IN_DIM * HD) return;
    int k = idx >> 7;
    int j = idx & 127;
    g_wtin[idx] = (j < DD) ? w_in[k * DD + j] : 0.f;
}

// ---------------- GEMM: P[n][j] = sum_k U[n][k] * WT[k][j] (+ bias) ----------------
// 128 threads (one per output column), 16 rows per block, row tile staged in smem.
template <int K, bool HASBIAS>
__global__ void __launch_bounds__(128) gemm_kernel(const float* __restrict__ U, int ldu,
                                                   const float* __restrict__ WT,
                                                   const float* __restrict__ bias,
                                                   float* __restrict__ P) {
    __shared__ __align__(16) float xs[16 * K];
    int j = threadIdx.x;
    int row0 = blockIdx.x * 16;
    for (int i = j; i < 16 * K; i += 128) {
        int m = i / K, k = i - m * K;
        int r = row0 + m;
        xs[i] = (r < NN) ? U[(size_t)r * ldu + k] : 0.f;
    }
    __syncthreads();
    float acc[16];
#pragma unroll
    for (int m = 0; m < 16; m++) acc[m] = 0.f;
    for (int k4 = 0; k4 < K / 4; k4++) {
        float w0 = WT[(k4 * 4 + 0) * HD + j];
        float w1 = WT[(k4 * 4 + 1) * HD + j];
        float w2 = WT[(k4 * 4 + 2) * HD + j];
        float w3 = WT[(k4 * 4 + 3) * HD + j];
#pragma unroll
        for (int m = 0; m < 16; m++) {
            float4 xv = *(const float4*)&xs[m * K + k4 * 4];
            acc[m] = fmaf(xv.x, w0, acc[m]);
            acc[m] = fmaf(xv.y, w1, acc[m]);
            acc[m] = fmaf(xv.z, w2, acc[m]);
            acc[m] = fmaf(xv.w, w3, acc[m]);
        }
    }
    float bj = 0.f;
    if (HASBIAS && j < DD) bj = bias[j];
#pragma unroll
    for (int m = 0; m < 16; m++) {
        int r = row0 + m;
        if (r < NN) P[(size_t)r * HD + j] = (j < DD) ? acc[m] + bj : 0.f;
    }
}

// ---------------- warp-per-node elementwise kernels ----------------

// out = proj(expmap0([0, P]))  — P spatial at slots 0..126; out = [t, s...] slots 0..127
__global__ void expmap_kernel(const float* __restrict__ P, float* __restrict__ out,
                              const float* __restrict__ cptr) {
    int warp = (blockIdx.x * blockDim.x + threadIdx.x) >> 5;
    int lane = threadIdx.x & 31;
    if (warp >= NN) return;
    float c = cptr[0], sc = sqrtf(c);
    float4 v = ((const float4*)(P + (size_t)warp * HD))[lane];
    float s = warp_sum(v.x * v.x + v.y * v.y + v.z * v.z + v.w * v.w);
    float n = fmaxf(sqrtf(s), 1e-9f);
    float sh = sc * sinhf(n / sc) / n;
    float wprev = __shfl_up_sync(0xffffffffu, v.w, 1);
    float4 o;
    o.x = (lane == 0) ? 0.f : sh * wprev;
    o.y = sh * v.x; o.z = sh * v.y; o.w = sh * v.z;
    // proj: time = sqrt(c + sum(spatial^2)) computed from stored components (faithful)
    float ss = warp_sum(((lane == 0) ? 0.f : o.x * o.x) + o.y * o.y + o.z * o.z + o.w * o.w);
    if (lane == 0) o.x = sqrtf(c + ss);
    ((float4*)(out + (size_t)warp * HD))[lane] = o;
}

// U = logmap0(H) spatial (slots 0..126, slot127 = 0)
__global__ void lognode_kernel(const float* __restrict__ H, float* __restrict__ U,
                               const float* __restrict__ cptr) {
    int warp = (blockIdx.x * blockDim.x + threadIdx.x) >> 5;
    int lane = threadIdx.x & 31;
    if (warp >= NN) return;
    float c = cptr[0], sc = sqrtf(c);
    float4 v = ((const float4*)(H + (size_t)warp * HD))[lane];
    float x0 = __shfl_sync(0xffffffffu, v.x, 0);
    float px = (lane == 0) ? 0.f : v.x * v.x;
    float s = warp_sum(px + v.y * v.y + v.z * v.z + v.w * v.w);
    float yn = fmaxf(sqrtf(s), 1e-9f);
    float d = sc * acoshf(fmaxf(x0 / sc, 1.f + EPSF));
    float a = d / yn;
    float nx = __shfl_down_sync(0xffffffffu, v.x, 1);
    float4 o;
    o.x = a * v.y; o.y = a * v.z; o.z = a * v.w;
    o.w = (lane == 31) ? 0.f : a * nx;
    ((float4*)(U + (size_t)warp * HD))[lane] = o;
}

// warp per edge: att = exp(-dist(hl[s], hl[d])), m[s] += att * h[d]
__global__ void edge_kernel(const int* __restrict__ ei, const float* __restrict__ hl,
                            const float* __restrict__ h, float* __restrict__ m,
                            const float* __restrict__ cptr) {
    int warp = (blockIdx.x * blockDim.x + threadIdx.x) >> 5;
    int lane = threadIdx.x & 31;
    if (warp >= EE) return;
    float c = cptr[0], sc = sqrtf(c);
    int s = ei[warp], d = ei[EE + warp];
    float4 a = ((const float4*)(hl + (size_t)s * HD))[lane];
    float4 b = ((const float4*)(hl + (size_t)d * HD))[lane];
    float p = ((lane == 0) ? -a.x * b.x : a.x * b.x) + a.y * b.y + a.z * b.z + a.w * b.w;
    p = warp_sum(p);
    float val = fmaxf(-p / c, 1.f + EPSF);
    float att = expf(-sc * acoshf(val));
    float4 hv = ((const float4*)(h + (size_t)d * HD))[lane];
    float* mr = m + (size_t)s * HD + lane * 4;
    atomicAdd(mr + 0, att * hv.x);
    atomicAdd(mr + 1, att * hv.y);
    atomicAdd(mr + 2, att * hv.z);
    atomicAdd(mr + 3, att * hv.w);
}

// GIN combine: h = proj(expmap0(logmap0(proj(centroid)) + (1+eps)*logmap0(proj(h))))
__global__ void combine_kernel(const float* __restrict__ Mv, float* __restrict__ H,
                               const float* __restrict__ cptr, const float* __restrict__ epsp,
                               int l) {
    int warp = (blockIdx.x * blockDim.x + threadIdx.x) >> 5;
    int lane = threadIdx.x & 31;
    if (warp >= NN) return;
    float c = cptr[0], sc = sqrtf(c), ep = epsp[l];
    float4 mv = ((const float4*)(Mv + (size_t)warp * HD))[lane];
    float4 hv = ((const float4*)(H + (size_t)warp * HD))[lane];
    float m0 = __shfl_sync(0xffffffffu, mv.x, 0);
    float pm = warp_sum(((lane == 0) ? 0.f : mv.x * mv.x) + mv.y * mv.y + mv.z * mv.z + mv.w * mv.w);
    float denom = sqrtf(fmaxf(m0 * m0 - pm, 1e-9f));
    float r = sc / denom;
    float ax = r * mv.x, ay = r * mv.y, az = r * mv.z, aw = r * mv.w;  // agg components
    float ssum = warp_sum(((lane == 0) ? 0.f : ax * ax) + ay * ay + az * az + aw * aw);
    float t = sqrtf(c + ssum);                   // proj time of agg
    float yn_a = fmaxf(sqrtf(ssum), 1e-9f);
    float d1 = sc * acoshf(fmaxf(t / sc, 1.f + EPSF));
    float cA = d1 / yn_a;
    float ph = warp_sum(((lane == 0) ? 0.f : hv.x * hv.x) + hv.y * hv.y + hv.z * hv.z + hv.w * hv.w);
    float hp0 = sqrtf(c + ph);                   // proj(h) time
    float yn_h = fmaxf(sqrtf(ph), 1e-9f);
    float d2 = sc * acoshf(fmaxf(hp0 / sc, 1.f + EPSF));
    float cH = (1.f + ep) * d2 / yn_h;
    float4 vv;
    vv.x = (lane == 0) ? 0.f : cA * ax + cH * hv.x;
    vv.y = cA * ay + cH * hv.y;
    vv.z = cA * az + cH * hv.z;
    vv.w = cA * aw + cH * hv.w;
    float pv = warp_sum(vv.x * vv.x + vv.y * vv.y + vv.z * vv.z + vv.w * vv.w);
    float n = fmaxf(sqrtf(pv), 1e-9f);
    float sh = sc * sinhf(n / sc) / n;
    float4 o;
    o.x = (lane == 0) ? 0.f : sh * vv.x;
    o.y = sh * vv.y; o.z = sh * vv.z; o.w = sh * vv.w;
    float so = warp_sum(((lane == 0) ? 0.f : o.x * o.x) + o.y * o.y + o.z * o.z + o.w * o.w);
    if (lane == 0) o.x = sqrtf(c + so);
    ((float4*)(H + (size_t)warp * HD))[lane] = o;
}

// MLP epilogue: H = hyp_act(proj(expmap0([0,P])))  (hyp_act output has NO trailing proj)
__global__ void mlp_epi_kernel(const float* __restrict__ P, float* __restrict__ H,
                               const float* __restrict__ cptr) {
    int warp = (blockIdx.x * blockDim.x + threadIdx.x) >> 5;
    int lane = threadIdx.x & 31;
    if (warp >= NN) return;
    float c = cptr[0], sc = sqrtf(c);
    float4 v = ((const float4*)(P + (size_t)warp * HD))[lane];
    float s = warp_sum(v.x * v.x + v.y * v.y + v.z * v.z + v.w * v.w);
    float n1 = fmaxf(sqrtf(s), 1e-9f);
    float sh1 = sc * sinhf(n1 / sc) / n1;
    float sx = sh1 * v.x, sy = sh1 * v.y, sz = sh1 * v.z, sw = sh1 * v.w;  // X spatial comps
    float ssum = warp_sum(sx * sx + sy * sy + sz * sz + sw * sw);          // slot127 contributes 0
    float x0 = sqrtf(c + ssum);                                            // proj time (faithful)
    float yn = fmaxf(sqrtf(ssum), 1e-9f);
    float d = sc * acoshf(fmaxf(x0 / sc, 1.f + EPSF));
    float cf = d / yn;
    float tx = tanhf(cf * sx), ty = tanhf(cf * sy), tz = tanhf(cf * sz), tw = tanhf(cf * sw);
    float s2 = warp_sum(tx * tx + ty * ty + tz * tz + tw * tw);
    float n2 = fmaxf(sqrtf(s2), 1e-9f);
    float sh2 = sc * sinhf(n2 / sc) / n2;
    float wprev = __shfl_up_sync(0xffffffffu, tw, 1);
    float4 o;
    o.x = (lane == 0) ? sc * coshf(n2 / sc) : sh2 * wprev;  // expmap0 time (no proj, exact formula)
    o.y = sh2 * tx; o.z = sh2 * ty; o.w = sh2 * tz;
    ((float4*)(H + (size_t)warp * HD))[lane] = o;
}

// pooled[batch[n], loff + i] += logmap0(h[n])[i]
__global__ void pool_kernel(const float* __restrict__ H, const int* __restrict__ batch,
                            const float* __restrict__ cptr, float* __restrict__ out, int loff) {
    int warp = (blockIdx.x * blockDim.x + threadIdx.x) >> 5;
    int lane = threadIdx.x & 31;
    if (warp >= NN) return;
    float c = cptr[0], sc = sqrtf(c);
    float4 v = ((const float4*)(H + (size_t)warp * HD))[lane];
    float x0 = __shfl_sync(0xffffffffu, v.x, 0);
    float p = warp_sum(((lane == 0) ? 0.f : v.x * v.x) + v.y * v.y + v.z * v.z + v.w * v.w);
    float yn = fmaxf(sqrtf(p), 1e-9f);
    float d = sc * acoshf(fmaxf(x0 / sc, 1.f + EPSF));
    float a = d / yn;
    int g = batch[warp];
    float* o = out + (size_t)g * (2 * HD) + loff + lane * 4;
    if (lane != 0) atomicAdd(o + 0, a * v.x);  // comp0 of logmap0 is exactly 0: skip
    atomicAdd(o + 1, a * v.y);
    atomicAdd(o + 2, a * v.z);
    atomicAdd(o + 3, a * v.w);
}

// ---------------- host launcher ----------------
extern "C" void kernel_launch(void* const* d_in, const int* in_sizes, int n_in,
                              void* d_out, int out_size) {
    (void)in_sizes; (void)n_in; (void)out_size;
    const float* x     = (const float*)d_in[0];
    const float* c     = (const float*)d_in[1];
    const float* w_in  = (const float*)d_in[2];
    const float* att_w = (const float*)d_in[3];
    const float* att_b = (const float*)d_in[4];
    const float* eps   = (const float*)d_in[5];
    const float* mlp_w = (const float*)d_in[6];
    const float* mlp_b = (const float*)d_in[7];
    const int*   ei    = (const int*)d_in[8];
    const int*   batch = (const int*)d_in[9];
    float* out = (float*)d_out;

    float *ph, *pu, *pp, *phl, *pm, *pwt, *pwtin;
    cudaGetSymbolAddress((void**)&ph, g_h);
    cudaGetSymbolAddress((void**)&pu, g_u);
    cudaGetSymbolAddress((void**)&pp, g_p);
    cudaGetSymbolAddress((void**)&phl, g_hl);
    cudaGetSymbolAddress((void**)&pm, g_m);
    cudaGetSymbolAddress((void**)&pwt, g_wt);
    cudaGetSymbolAddress((void**)&pwtin, g_wtin);

    const int NB = (NN + 7) / 8;    // warp-per-node blocks (256 threads = 8 warps)
    const int EB = (EE + 7) / 8;    // warp-per-edge blocks
    const int GB = (NN + 15) / 16;  // GEMM blocks

    zero4_kernel<<<(GG * 2 * HD / 4 + 255) / 256, 256>>>((float4*)out, GG * 2 * HD / 4);
    prep_weights<<<(6 * HD * HD + 255) / 256, 256>>>(att_w, mlp_w);
    prep_win<<<(IN_DIM * HD + 255) / 256, 256>>>(w_in);

    gemm_kernel<IN_DIM, false><<<GB, 128>>>(x, IN_DIM, pwtin, nullptr, pp);
    expmap_kernel<<<NB, 256>>>(pp, ph, c);

    for (int l = 0; l < 2; l++) {
        // attention linear -> hl
        lognode_kernel<<<NB, 256>>>(ph, pu, c);
        gemm_kernel<HD, true><<<GB, 128>>>(pu, HD, pwt + l * HD * HD, att_b + l * DD, pp);
        expmap_kernel<<<NB, 256>>>(pp, phl, c);
        // centroid aggregation
        zero4_kernel<<<(NN * HD / 4 + 255) / 256, 256>>>((float4*)pm, NN * HD / 4);
        edge_kernel<<<EB, 256>>>(ei, phl, ph, pm, c);
        combine_kernel<<<NB, 256>>>(pm, ph, c, eps, l);
        // MLP (2 hyp_linear+hyp_act)
        for (int m = 0; m < 2; m++) {
            lognode_kernel<<<NB, 256>>>(ph, pu, c);
            gemm_kernel<HD, true><<<GB, 128>>>(pu, HD, pwt + (2 + l * 2 + m) * HD * HD,
                                               mlp_b + (l * 2 + m) * DD, pp);
            mlp_epi_kernel<<<NB, 256>>>(pp, ph, c);
        }
        // pooled readout for this layer
        pool_kernel<<<NB, 256>>>(ph, batch, c, out, l * HD);
    }
}

// round 4
// speedup vs baseline: 1.4483x; 1.4483x over previous
#include <cuda_runtime.h>
#include <math.h>

#define NN 50000
#define EE 800000
#define IN_DIM 200
#define HD 128
#define DD 127
#define GG 512
#define EPSF 1e-5f

// ---------------- scratch (device globals; no allocation allowed) ----------------
__device__ float g_h[NN * HD];      // current node features (hyperboloid points)
__device__ float g_u[NN * HD];      // logmap0 spatial (slots 0..126, slot 127 = 0)
__device__ float g_p[NN * HD];      // GEMM output (slots 0..126, slot 127 = 0)
__device__ float g_hl[NN * HD];     // attention-linear hyperboloid points
__device__ float g_m[NN * HD];      // centroid accumulator
__device__ float g_wt[6 * HD * HD]; // transposed+padded layer weights (att l0, att l1, mlp 00,01,10,11)
__device__ float g_wtin[IN_DIM * HD]; // padded input weight

__device__ __forceinline__ float warp_sum(float v) {
#pragma unroll
    for (int o = 16; o; o >>= 1) v += __shfl_xor_sync(0xffffffffu, v, o);
    return v;
}

__device__ __forceinline__ void red_v4(float* p, float a, float b, float c, float d) {
    asm volatile("red.global.add.v4.f32 [%0], {%1,%2,%3,%4};"
                 :: "l"(p), "f"(a), "f"(b), "f"(c), "f"(d) : "memory");
}

// ---------------- utility kernels ----------------
__global__ void zero4_kernel(float4* __restrict__ p, int n4) {
    int i = blockIdx.x * blockDim.x + threadIdx.x;
    if (i < n4) p[i] = make_float4(0.f, 0.f, 0.f, 0.f);
}

// wt[w][k*128 + j] = W_w[j][k]  (transpose so GEMM loads are coalesced over j)
__global__ void prep_weights(const float* __restrict__ att_w, const float* __restrict__ mlp_w) {
    int idx = blockIdx.x * blockDim.x + threadIdx.x;
    if (idx >= 6 * HD * HD) return;
    int w = idx >> 14;
    int k = (idx >> 7) & 127;
    int j = idx & 127;
    float val = 0.f;
    if (k < DD && j < DD) {
        const float* src = (w < 2) ? (att_w + w * DD * DD) : (mlp_w + (w - 2) * DD * DD);
        val = src[j * DD + k];
    }
    g_wt[idx] = val;
}

__global__ void prep_win(const float* __restrict__ w_in) {
    int idx = blockIdx.x * blockDim.x + threadIdx.x;
    if (idx >= IN_DIM * HD) return;
    int k = idx >> 7;
    int j = idx & 127;
    g_wtin[idx] = (j < DD) ? w_in[k * DD + j] : 0.f;
}

// ---------------- GEMM: P[n][j] = sum_k U[n][k] * WT[k][j] (+ bias) ----------------
// 256 threads. Tile: TM rows x 128 cols. Thread (cg = tid&31, rg = tid>>5) computes
// RPT rows x 4 cols in registers. x tile staged in smem (all x reads are warp
// broadcasts -> conflict-free); weights streamed as coalesced float4 LDGs.
template <int K, bool HASBIAS>
__global__ void __launch_bounds__(256) gemm_kernel(const float* __restrict__ U,
                                                   const float* __restrict__ WT,
                                                   const float* __restrict__ bias,
                                                   float* __restrict__ P) {
    constexpr int TM = (K > 128) ? 56 : 64;   // keep static smem under 48KB
    constexpr int RPT = TM / 8;
    constexpr int K4 = K / 4;
    __shared__ __align__(16) float4 xs[TM * K4];
    int tid = threadIdx.x;
    int cg = tid & 31;          // column group: cols 4*cg .. 4*cg+3
    int rg = tid >> 5;          // row group: rows rg*RPT .. rg*RPT+RPT-1
    int row0 = blockIdx.x * TM;

    for (int i = tid; i < TM * K4; i += 256) {
        int m = i / K4, k4 = i - m * K4;
        int r = row0 + m;
        xs[i] = (r < NN) ? ((const float4*)(U + (size_t)r * K))[k4]
                         : make_float4(0.f, 0.f, 0.f, 0.f);
    }
    __syncthreads();

    float acc[RPT][4];
#pragma unroll
    for (int r = 0; r < RPT; r++) {
        acc[r][0] = 0.f; acc[r][1] = 0.f; acc[r][2] = 0.f; acc[r][3] = 0.f;
    }

    const float4* W4 = (const float4*)WT;
#pragma unroll 4
    for (int kq = 0; kq < K4; kq++) {
        float4 w0 = W4[(kq * 4 + 0) * 32 + cg];
        float4 w1 = W4[(kq * 4 + 1) * 32 + cg];
        float4 w2 = W4[(kq * 4 + 2) * 32 + cg];
        float4 w3 = W4[(kq * 4 + 3) * 32 + cg];
#pragma unroll
        for (int r = 0; r < RPT; r++) {
            float4 xv = xs[(rg * RPT + r) * K4 + kq];
            acc[r][0] = fmaf(xv.x, w0.x, acc[r][0]);
            acc[r][1] = fmaf(xv.x, w0.y, acc[r][1]);
            acc[r][2] = fmaf(xv.x, w0.z, acc[r][2]);
            acc[r][3] = fmaf(xv.x, w0.w, acc[r][3]);
            acc[r][0] = fmaf(xv.y, w1.x, acc[r][0]);
            acc[r][1] = fmaf(xv.y, w1.y, acc[r][1]);
            acc[r][2] = fmaf(xv.y, w1.z, acc[r][2]);
            acc[r][3] = fmaf(xv.y, w1.w, acc[r][3]);
            acc[r][0] = fmaf(xv.z, w2.x, acc[r][0]);
            acc[r][1] = fmaf(xv.z, w2.y, acc[r][1]);
            acc[r][2] = fmaf(xv.z, w2.z, acc[r][2]);
            acc[r][3] = fmaf(xv.z, w2.w, acc[r][3]);
            acc[r][0] = fmaf(xv.w, w3.x, acc[r][0]);
            acc[r][1] = fmaf(xv.w, w3.y, acc[r][1]);
            acc[r][2] = fmaf(xv.w, w3.z, acc[r][2]);
            acc[r][3] = fmaf(xv.w, w3.w, acc[r][3]);
        }
    }

    float4 bv = make_float4(0.f, 0.f, 0.f, 0.f);
    if (HASBIAS) {
        int j0 = 4 * cg;
        bv.x = (j0 + 0 < DD) ? bias[j0 + 0] : 0.f;
        bv.y = (j0 + 1 < DD) ? bias[j0 + 1] : 0.f;
        bv.z = (j0 + 2 < DD) ? bias[j0 + 2] : 0.f;
        bv.w = (j0 + 3 < DD) ? bias[j0 + 3] : 0.f;
    }
#pragma unroll
    for (int r = 0; r < RPT; r++) {
        int gr = row0 + rg * RPT + r;
        if (gr < NN) {
            float4 res;
            res.x = acc[r][0] + bv.x;
            res.y = acc[r][1] + bv.y;
            res.z = acc[r][2] + bv.z;
            res.w = (cg == 31) ? 0.f : acc[r][3] + bv.w;  // col 127 is padding
            ((float4*)(P + (size_t)gr * HD))[cg] = res;
        }
    }
}

// ---------------- warp-per-node elementwise kernels ----------------

// out = proj(expmap0([0, P]))  — P spatial at slots 0..126; out = [t, s...] slots 0..127
__global__ void expmap_kernel(const float* __restrict__ P, float* __restrict__ out,
                              const float* __restrict__ cptr) {
    int warp = (blockIdx.x * blockDim.x + threadIdx.x) >> 5;
    int lane = threadIdx.x & 31;
    if (warp >= NN) return;
    float c = cptr[0], sc = sqrtf(c);
    float4 v = ((const float4*)(P + (size_t)warp * HD))[lane];
    float s = warp_sum(v.x * v.x + v.y * v.y + v.z * v.z + v.w * v.w);
    float n = fmaxf(sqrtf(s), 1e-9f);
    float sh = sc * sinhf(n / sc) / n;
    float wprev = __shfl_up_sync(0xffffffffu, v.w, 1);
    float4 o;
    o.x = (lane == 0) ? 0.f : sh * wprev;
    o.y = sh * v.x; o.z = sh * v.y; o.w = sh * v.z;
    // proj: time = sqrt(c + sum(spatial^2)) computed from stored components (faithful)
    float ss = warp_sum(((lane == 0) ? 0.f : o.x * o.x) + o.y * o.y + o.z * o.z + o.w * o.w);
    if (lane == 0) o.x = sqrtf(c + ss);
    ((float4*)(out + (size_t)warp * HD))[lane] = o;
}

// U = logmap0(H) spatial (slots 0..126, slot127 = 0)
__global__ void lognode_kernel(const float* __restrict__ H, float* __restrict__ U,
                               const float* __restrict__ cptr) {
    int warp = (blockIdx.x * blockDim.x + threadIdx.x) >> 5;
    int lane = threadIdx.x & 31;
    if (warp >= NN) return;
    float c = cptr[0], sc = sqrtf(c);
    float4 v = ((const float4*)(H + (size_t)warp * HD))[lane];
    float x0 = __shfl_sync(0xffffffffu, v.x, 0);
    float px = (lane == 0) ? 0.f : v.x * v.x;
    float s = warp_sum(px + v.y * v.y + v.z * v.z + v.w * v.w);
    float yn = fmaxf(sqrtf(s), 1e-9f);
    float d = sc * acoshf(fmaxf(x0 / sc, 1.f + EPSF));
    float a = d / yn;
    float nx = __shfl_down_sync(0xffffffffu, v.x, 1);
    float4 o;
    o.x = a * v.y; o.y = a * v.z; o.z = a * v.w;
    o.w = (lane == 31) ? 0.f : a * nx;
    ((float4*)(U + (size_t)warp * HD))[lane] = o;
}

// warp per edge: att = exp(-dist(hl[s], hl[d])), m[s] += att * h[d]
__global__ void edge_kernel(const int* __restrict__ ei, const float* __restrict__ hl,
                            const float* __restrict__ h, float* __restrict__ m,
                            const float* __restrict__ cptr) {
    int warp = (blockIdx.x * blockDim.x + threadIdx.x) >> 5;
    int lane = threadIdx.x & 31;
    if (warp >= EE) return;
    float c = cptr[0], sc = sqrtf(c);
    int s = ei[warp], d = ei[EE + warp];
    float4 a = ((const float4*)(hl + (size_t)s * HD))[lane];
    float4 b = ((const float4*)(hl + (size_t)d * HD))[lane];
    float p = ((lane == 0) ? -a.x * b.x : a.x * b.x) + a.y * b.y + a.z * b.z + a.w * b.w;
    p = warp_sum(p);
    float val = fmaxf(-p / c, 1.f + EPSF);
    float att = expf(-sc * acoshf(val));
    float4 hv = ((const float4*)(h + (size_t)d * HD))[lane];
    red_v4(m + (size_t)s * HD + lane * 4, att * hv.x, att * hv.y, att * hv.z, att * hv.w);
}

// GIN combine: h = proj(expmap0(logmap0(proj(centroid)) + (1+eps)*logmap0(proj(h))))
__global__ void combine_kernel(const float* __restrict__ Mv, float* __restrict__ H,
                               const float* __restrict__ cptr, const float* __restrict__ epsp,
                               int l) {
    int warp = (blockIdx.x * blockDim.x + threadIdx.x) >> 5;
    int lane = threadIdx.x & 31;
    if (warp >= NN) return;
    float c = cptr[0], sc = sqrtf(c), ep = epsp[l];
    float4 mv = ((const float4*)(Mv + (size_t)warp * HD))[lane];
    float4 hv = ((const float4*)(H + (size_t)warp * HD))[lane];
    float m0 = __shfl_sync(0xffffffffu, mv.x, 0);
    float pm = warp_sum(((lane == 0) ? 0.f : mv.x * mv.x) + mv.y * mv.y + mv.z * mv.z + mv.w * mv.w);
    float denom = sqrtf(fmaxf(m0 * m0 - pm, 1e-9f));
    float r = sc / denom;
    float ax = r * mv.x, ay = r * mv.y, az = r * mv.z, aw = r * mv.w;  // agg components
    float ssum = warp_sum(((lane == 0) ? 0.f : ax * ax) + ay * ay + az * az + aw * aw);
    float t = sqrtf(c + ssum);                   // proj time of agg
    float yn_a = fmaxf(sqrtf(ssum), 1e-9f);
    float d1 = sc * acoshf(fmaxf(t / sc, 1.f + EPSF));
    float cA = d1 / yn_a;
    float ph = warp_sum(((lane == 0) ? 0.f : hv.x * hv.x) + hv.y * hv.y + hv.z * hv.z + hv.w * hv.w);
    float hp0 = sqrtf(c + ph);                   // proj(h) time
    float yn_h = fmaxf(sqrtf(ph), 1e-9f);
    float d2 = sc * acoshf(fmaxf(hp0 / sc, 1.f + EPSF));
    float cH = (1.f + ep) * d2 / yn_h;
    float4 vv;
    vv.x = (lane == 0) ? 0.f : cA * ax + cH * hv.x;
    vv.y = cA * ay + cH * hv.y;
    vv.z = cA * az + cH * hv.z;
    vv.w = cA * aw + cH * hv.w;
    float pv = warp_sum(vv.x * vv.x + vv.y * vv.y + vv.z * vv.z + vv.w * vv.w);
    float n = fmaxf(sqrtf(pv), 1e-9f);
    float sh = sc * sinhf(n / sc) / n;
    float4 o;
    o.x = (lane == 0) ? 0.f : sh * vv.x;
    o.y = sh * vv.y; o.z = sh * vv.z; o.w = sh * vv.w;
    float so = warp_sum(((lane == 0) ? 0.f : o.x * o.x) + o.y * o.y + o.z * o.z + o.w * o.w);
    if (lane == 0) o.x = sqrtf(c + so);
    ((float4*)(H + (size_t)warp * HD))[lane] = o;
}

// MLP epilogue: H = hyp_act(proj(expmap0([0,P])))  (hyp_act output has NO trailing proj)
__global__ void mlp_epi_kernel(const float* __restrict__ P, float* __restrict__ H,
                               const float* __restrict__ cptr) {
    int warp = (blockIdx.x * blockDim.x + threadIdx.x) >> 5;
    int lane = threadIdx.x & 31;
    if (warp >= NN) return;
    float c = cptr[0], sc = sqrtf(c);
    float4 v = ((const float4*)(P + (size_t)warp * HD))[lane];
    float s = warp_sum(v.x * v.x + v.y * v.y + v.z * v.z + v.w * v.w);
    float n1 = fmaxf(sqrtf(s), 1e-9f);
    float sh1 = sc * sinhf(n1 / sc) / n1;
    float sx = sh1 * v.x, sy = sh1 * v.y, sz = sh1 * v.z, sw = sh1 * v.w;  // X spatial comps
    float ssum = warp_sum(sx * sx + sy * sy + sz * sz + sw * sw);          // slot127 contributes 0
    float x0 = sqrtf(c + ssum);                                            // proj time (faithful)
    float yn = fmaxf(sqrtf(ssum), 1e-9f);
    float d = sc * acoshf(fmaxf(x0 / sc, 1.f + EPSF));
    float cf = d / yn;
    float tx = tanhf(cf * sx), ty = tanhf(cf * sy), tz = tanhf(cf * sz), tw = tanhf(cf * sw);
    float s2 = warp_sum(tx * tx + ty * ty + tz * tz + tw * tw);
    float n2 = fmaxf(sqrtf(s2), 1e-9f);
    float sh2 = sc * sinhf(n2 / sc) / n2;
    float wprev = __shfl_up_sync(0xffffffffu, tw, 1);
    float4 o;
    o.x = (lane == 0) ? sc * coshf(n2 / sc) : sh2 * wprev;  // expmap0 time (no proj, exact formula)
    o.y = sh2 * tx; o.z = sh2 * ty; o.w = sh2 * tz;
    ((float4*)(H + (size_t)warp * HD))[lane] = o;
}

// pooled[batch[n], loff + i] += logmap0(h[n])[i]
__global__ void pool_kernel(const float* __restrict__ H, const int* __restrict__ batch,
                            const float* __restrict__ cptr, float* __restrict__ out, int loff) {
    int warp = (blockIdx.x * blockDim.x + threadIdx.x) >> 5;
    int lane = threadIdx.x & 31;
    if (warp >= NN) return;
    float c = cptr[0], sc = sqrtf(c);
    float4 v = ((const float4*)(H + (size_t)warp * HD))[lane];
    float x0 = __shfl_sync(0xffffffffu, v.x, 0);
    float p = warp_sum(((lane == 0) ? 0.f : v.x * v.x) + v.y * v.y + v.z * v.z + v.w * v.w);
    float yn = fmaxf(sqrtf(p), 1e-9f);
    float d = sc * acoshf(fmaxf(x0 / sc, 1.f + EPSF));
    float a = d / yn;
    int g = batch[warp];
    // comp0 of logmap0 is exactly 0 for lane 0
    red_v4(out + (size_t)g * (2 * HD) + loff + lane * 4,
           (lane == 0) ? 0.f : a * v.x, a * v.y, a * v.z, a * v.w);
}

// ---------------- host launcher ----------------
extern "C" void kernel_launch(void* const* d_in, const int* in_sizes, int n_in,
                              void* d_out, int out_size) {
    (void)in_sizes; (void)n_in; (void)out_size;
    const float* x     = (const float*)d_in[0];
    const float* c     = (const float*)d_in[1];
    const float* w_in  = (const float*)d_in[2];
    const float* att_w = (const float*)d_in[3];
    const float* att_b = (const float*)d_in[4];
    const float* eps   = (const float*)d_in[5];
    const float* mlp_w = (const float*)d_in[6];
    const float* mlp_b = (const float*)d_in[7];
    const int*   ei    = (const int*)d_in[8];
    const int*   batch = (const int*)d_in[9];
    float* out = (float*)d_out;

    float *ph, *pu, *pp, *phl, *pm, *pwt, *pwtin;
    cudaGetSymbolAddress((void**)&ph, g_h);
    cudaGetSymbolAddress((void**)&pu, g_u);
    cudaGetSymbolAddress((void**)&pp, g_p);
    cudaGetSymbolAddress((void**)&phl, g_hl);
    cudaGetSymbolAddress((void**)&pm, g_m);
    cudaGetSymbolAddress((void**)&pwt, g_wt);
    cudaGetSymbolAddress((void**)&pwtin, g_wtin);

    const int NB = (NN + 7) / 8;        // warp-per-node blocks (256 threads = 8 warps)
    const int EB = (EE + 7) / 8;        // warp-per-edge blocks
    const int GB200 = (NN + 55) / 56;   // GEMM K=200 blocks (TM=56)
    const int GB128 = (NN + 63) / 64;   // GEMM K=128 blocks (TM=64)

    zero4_kernel<<<(GG * 2 * HD / 4 + 255) / 256, 256>>>((float4*)out, GG * 2 * HD / 4);
    prep_weights<<<(6 * HD * HD + 255) / 256, 256>>>(att_w, mlp_w);
    prep_win<<<(IN_DIM * HD + 255) / 256, 256>>>(w_in);

    gemm_kernel<IN_DIM, false><<<GB200, 256>>>(x, pwtin, nullptr, pp);
    expmap_kernel<<<NB, 256>>>(pp, ph, c);

    for (int l = 0; l < 2; l++) {
        // attention linear -> hl
        lognode_kernel<<<NB, 256>>>(ph, pu, c);
        gemm_kernel<HD, true><<<GB128, 256>>>(pu, pwt + l * HD * HD, att_b + l * DD, pp);
        expmap_kernel<<<NB, 256>>>(pp, phl, c);
        // centroid aggregation
        zero4_kernel<<<(NN * HD / 4 + 255) / 256, 256>>>((float4*)pm, NN * HD / 4);
        edge_kernel<<<EB, 256>>>(ei, phl, ph, pm, c);
        combine_kernel<<<NB, 256>>>(pm, ph, c, eps, l);
        // MLP (2 hyp_linear+hyp_act)
        for (int m = 0; m < 2; m++) {
            lognode_kernel<<<NB, 256>>>(ph, pu, c);
            gemm_kernel<HD, true><<<GB128, 256>>>(pu, pwt + (2 + l * 2 + m) * HD * HD,
                                                  mlp_b + (l * 2 + m) * DD, pp);
            mlp_epi_kernel<<<NB, 256>>>(pp, ph, c);
        }
        // pooled readout for this layer
        pool_kernel<<<NB, 256>>>(ph, batch, c, out, l * HD);
    }
}